// round 11
// baseline (speedup 1.0000x reference)
#include <cuda_runtime.h>
#include <cstdint>

// ---------------- problem shapes (fixed by the dataset) ----------------
constexpr int B    = 8;
constexpr int C    = 19;
constexpr int H    = 512;
constexpr int W    = 1024;
constexpr int HW   = H * W;            // 524288 = 2^19
constexpr int NPIX = B * HW;           // 4194304
constexpr int Hh   = 128;
constexpr int Wh   = 256;
constexpr int HhWh = Hh * Wh;          // 32768
constexpr int NHEAT = B * HhWh;        // 262144
constexpr int NBOX  = 8 * 64;          // 512

constexpr float OHEM_THRESH = 0.22314355513142097f;  // -log(0.8)
constexpr int   NBINS = 4096;
constexpr float BIN_SCALE = (float)NBINS / OHEM_THRESH;
constexpr float F32_TINY = 1.17549435e-38f;
constexpr float L2E  = 1.4426950408889634f;   // log2(e)
constexpr float LN2  = 0.6931471805599453f;   // ln(2)

// ---- pipelined OHEM geometry ----
constexpr int TILE_PIX     = 256;                    // pixels per tile
constexpr int NTILES       = NPIX / TILE_PIX;        // 16384
constexpr int TILES_PER_IMG = HW / TILE_PIX;         // 2048
constexpr int STAGES       = 2;
constexpr int STAGE_BYTES  = C * TILE_PIX * 4;       // 19456
constexpr int NBLOCKS      = 740;                    // 5 per SM on 148 SMs
constexpr int BLOCK_THREADS = 288;                   // 8 consumer warps + 1 producer
constexpr int FOCAL_BLOCKS = 256;                    // blocks 0..255 pre-do focal

// ---------------- device accumulators (zero at load; final block re-zeros
// them each run so graph replays stay deterministic) ----------------
__device__ double             g_sum_hard;
__device__ unsigned long long g_cnt_hard;
__device__ unsigned long long g_cnt_valid;
__device__ double             g_hist_sum[NBINS];
__device__ unsigned int       g_hist_cnt[NBINS];
__device__ double             g_pos_loss;
__device__ double             g_neg_loss;
__device__ double             g_npos;
__device__ double             g_reg_sum;
__device__ unsigned int       g_done;

__device__ __forceinline__ float ex2f(float x) {
    float r; asm("ex2.approx.ftz.f32 %0, %1;" : "=f"(r) : "f"(x)); return r;
}
__device__ __forceinline__ float lg2f(float x) {
    float r; asm("lg2.approx.ftz.f32 %0, %1;" : "=f"(r) : "f"(x)); return r;
}
__device__ __forceinline__ uint32_t smem_u32(const void* p) {
    uint32_t a;
    asm("{ .reg .u64 t; cvta.to.shared.u64 t, %1; cvt.u32.u64 %0, t; }" : "=r"(a) : "l"(p));
    return a;
}
__device__ __forceinline__ void mbar_init(uint32_t mbar, uint32_t count) {
    asm volatile("mbarrier.init.shared.b64 [%0], %1;" :: "r"(mbar), "r"(count) : "memory");
}
__device__ __forceinline__ void mbar_expect_tx(uint32_t mbar, uint32_t bytes) {
    asm volatile("mbarrier.arrive.expect_tx.shared.b64 _, [%0], %1;"
                 :: "r"(mbar), "r"(bytes) : "memory");
}
__device__ __forceinline__ void mbar_arrive(uint32_t mbar) {
    asm volatile("mbarrier.arrive.shared.b64 _, [%0];" :: "r"(mbar) : "memory");
}
__device__ __forceinline__ void bulk_g2s(uint32_t dst, const void* src,
                                         uint32_t bytes, uint32_t mbar) {
    asm volatile(
        "cp.async.bulk.shared::cluster.global.mbarrier::complete_tx::bytes [%0], [%1], %2, [%3];"
        :: "r"(dst), "l"(src), "r"(bytes), "r"(mbar) : "memory");
}
__device__ __forceinline__ void mbar_wait(uint32_t mbar, uint32_t phase) {
    uint32_t done;
    asm volatile(
        "{\n\t.reg .pred p;\n\t"
        "mbarrier.try_wait.parity.acquire.cta.shared::cta.b64 p, [%1], %2;\n\t"
        "selp.b32 %0, 1, 0, p;\n\t}"
        : "=r"(done) : "r"(mbar), "r"(phase) : "memory");
    while (!done) {
        asm volatile(
            "{\n\t.reg .pred p;\n\t"
            "mbarrier.try_wait.parity.acquire.cta.shared::cta.b64 p, [%1], %2, 0x989680;\n\t"
            "selp.b32 %0, 1, 0, p;\n\t}"
            : "=r"(done) : "r"(mbar), "r"(phase) : "memory");
    }
}

// ---------------- one fused, persistent, pipelined kernel ----------------
__global__ __launch_bounds__(BLOCK_THREADS, 5) void fused_loss_kernel(
    const float* __restrict__ seg,     const int*   __restrict__ masks,
    const float* __restrict__ hm_pred, const float* __restrict__ hm_tgt,
    const float* __restrict__ wh,      const float* __restrict__ bboxes,
    const int*   __restrict__ ct,      float* __restrict__ out)
{
    const int bid  = blockIdx.x;
    const int tid  = threadIdx.x;
    const int lane = tid & 31, wid = tid >> 5;

    __shared__ alignas(16) float s_stage[STAGES][C][TILE_PIX];   // 38912 B
    __shared__ alignas(8)  unsigned long long s_full[STAGES], s_empty[STAGES];
    __shared__ float    s_f0[9];
    __shared__ unsigned s_u0[9], s_u1[9];

    if (tid == 0) {
        #pragma unroll
        for (int s = 0; s < STAGES; s++) {
            mbar_init(smem_u32(&s_full[s]), 1);    // expect_tx arrival only
            mbar_init(smem_u32(&s_empty[s]), 8);   // one arrive per consumer warp
        }
    }
    __syncthreads();

    // tiles for this block, grid-strided: T = bid + i*NBLOCKS
    const int nt = (NTILES - bid + NBLOCKS - 1) / NBLOCKS;   // 22 or 23

    float    fs = 0.0f;
    unsigned hc = 0, vc = 0;

    if (wid == 8) {
        // =================== producer warp ===================
        for (int i = 0; i < nt; i++) {
            int s = i & 1;
            int k = i >> 1;
            mbar_wait(smem_u32(&s_empty[s]), (k & 1) ^ 1);   // first visit passes
            int T    = bid + i * NBLOCKS;
            int b    = T >> 11;                               // / TILES_PER_IMG
            int pix0 = (T & (TILES_PER_IMG - 1)) * TILE_PIX;
            const float* src = seg + (size_t)b * C * HW + pix0;
            if (lane == 0) mbar_expect_tx(smem_u32(&s_full[s]), STAGE_BYTES);
            __syncwarp();
            if (lane < C)
                bulk_g2s(smem_u32(&s_stage[s][lane][0]),
                         src + (size_t)lane * HW, TILE_PIX * 4,
                         smem_u32(&s_full[s]));
        }
    } else {
        // =================== consumer warps (256 threads) ===================
        // ---- pre-work: focal (bid<256) / regression (bid==256), no block sync ----
        if (bid < FOCAL_BLOCKS) {
            int i4 = bid * 256 + tid;                 // NHEAT/4 = 65536 float4s
            float4 pv  = __ldcs((const float4*)hm_pred + i4);
            float4 tv4 = __ldcs((const float4*)hm_tgt + i4);
            float pl = 0.0f, nl = 0.0f, np = 0.0f;
            const float* pp = &pv.x;
            const float* tp = &tv4.x;
            #pragma unroll
            for (int k = 0; k < 4; k++) {
                float p = fmaxf(pp[k], F32_TINY);
                float t = tp[k];
                if (t == 1.0f) {
                    float om = 1.0f - p;
                    pl += lg2f(p) * LN2 * om * om;
                    np += 1.0f;
                } else {
                    float omt = 1.0f - t;
                    float wgt = omt * omt; wgt *= wgt;
                    nl += lg2f(1.0f - p + F32_TINY) * LN2 * p * p * wgt;
                }
            }
            #pragma unroll
            for (int o = 16; o > 0; o >>= 1) {
                pl += __shfl_xor_sync(0xffffffffu, pl, o);
                nl += __shfl_xor_sync(0xffffffffu, nl, o);
                np += __shfl_xor_sync(0xffffffffu, np, o);
            }
            if (lane == 0) {
                atomicAdd(&g_pos_loss, (double)pl);
                atomicAdd(&g_neg_loss, (double)nl);
                atomicAdd(&g_npos,     (double)np);
            }
        } else if (bid == FOCAL_BLOCKS) {
            float l1 = 0.0f;
            #pragma unroll
            for (int r = 0; r < 2; r++) {
                int i = tid + r * 256;
                int b = i >> 6;
                int x = ct[i * 2 + 0];
                int y = ct[i * 2 + 1];
                const float* whb = wh + (size_t)b * 2 * HhWh;
                float v0 = whb[y * Wh + x];
                float v1 = whb[HhWh + y * Wh + x];
                const float* bb = bboxes + (size_t)i * 4;
                float w = bb[2] - bb[0];
                float h = bb[3] - bb[1];
                l1 += fabsf(v0 - w) + fabsf(v1 - h);
            }
            #pragma unroll
            for (int o = 16; o > 0; o >>= 1) l1 += __shfl_xor_sync(0xffffffffu, l1, o);
            if (lane == 0) atomicAdd(&g_reg_sum, (double)l1);
        }

        // ---- OHEM tile loop ----
        for (int i = 0; i < nt; i++) {
            int s = i & 1;
            int k = i >> 1;
            int T = bid + i * NBLOCKS;
            int t = __ldcs(masks + (size_t)T * TILE_PIX + tid);  // prefetch before wait
            mbar_wait(smem_u32(&s_full[s]), k & 1);

            const float* st = &s_stage[s][0][0];
            float sum = 0.0f;
            #pragma unroll
            for (int c = 0; c < C; c++)
                sum += ex2f(st[c * TILE_PIX + tid] * L2E);

            bool valid = (t != 255);
            float xt = valid ? st[t * TILE_PIX + tid] : 0.0f;   // conflict-free SMEM gather
            float ce = valid ? __fmaf_rn(lg2f(sum), LN2, -xt) : 0.0f;
            bool hd = ce > OHEM_THRESH;

            fs += hd ? ce : 0.0f;
            hc += (unsigned)hd;
            vc += (unsigned)valid;
            if (!hd) {   // rare: ce <= THRESH -> global histogram
                int bin = min(max((int)(ce * BIN_SCALE), 0), NBINS - 1);
                atomicAdd(&g_hist_cnt[bin], 1u);
                atomicAdd(&g_hist_sum[bin], (double)ce);
            }

            __syncwarp();                      // all lanes done reading stage
            if (lane == 0) mbar_arrive(smem_u32(&s_empty[s]));
        }
    }

    // =================== block reduction (producer contributes zeros) ===========
    #pragma unroll
    for (int o = 16; o > 0; o >>= 1) {
        fs += __shfl_xor_sync(0xffffffffu, fs, o);
        hc += __shfl_xor_sync(0xffffffffu, hc, o);
        vc += __shfl_xor_sync(0xffffffffu, vc, o);
    }
    if (lane == 0) { s_f0[wid] = fs; s_u0[wid] = hc; s_u1[wid] = vc; }
    __syncthreads();
    if (tid == 0) {
        double ts = 0.0; unsigned th = 0, tv = 0;
        #pragma unroll
        for (int i = 0; i < 9; i++) { ts += (double)s_f0[i]; th += s_u0[i]; tv += s_u1[i]; }
        if (th | tv) {
            atomicAdd(&g_sum_hard, ts);
            atomicAdd(&g_cnt_hard, (unsigned long long)th);
            atomicAdd(&g_cnt_valid, (unsigned long long)tv);
        }
    }

    // ===================== last-block election =====================
    __shared__ bool s_last;
    __syncthreads();
    if (tid == 0) {
        __threadfence();
        unsigned prev = atomicAdd(&g_done, 1u);
        s_last = (prev == (unsigned)(NBLOCKS - 1));
    }
    __syncthreads();
    if (!s_last) return;
    __threadfence();

    __shared__ float s_out[4];
    if (tid == 0) {
        // classification (OHEM)
        unsigned long long nmin = g_cnt_valid / 16ull;
        double k, top;
        if (g_cnt_hard >= nmin) {
            k = (double)g_cnt_hard;
            top = g_sum_hard;
        } else {
            k = (double)nmin;
            top = g_sum_hard;
            double need = (double)(nmin - g_cnt_hard);
            for (int bin = NBINS - 1; bin >= 0 && need > 0.0; --bin) {
                unsigned c = g_hist_cnt[bin];
                if (!c) continue;
                if ((double)c <= need) { top += g_hist_sum[bin]; need -= (double)c; }
                else                   { top += g_hist_sum[bin] * (need / (double)c); need = 0.0; }
            }
        }
        float cls = (k > 0.0) ? (float)(top / k) : 0.0f;

        // centerness (focal)
        double npos = g_npos;
        double fl = (npos == 0.0) ? -g_neg_loss
                                  : -(g_pos_loss + g_neg_loss) / fmax(npos, 1.0);
        float centerness = (float)fl;

        // bbox
        float regression = (float)g_reg_sum * 0.7f;
        float bbox = regression / ((float)NBOX + 1e-7f) * 0.1f;
        float localization = (centerness + bbox) * 1.0f;

        s_out[0] = cls;
        s_out[1] = localization;
        s_out[2] = centerness;
        s_out[3] = bbox;
    }
    __syncthreads();

    if (tid < 4) out[tid] = s_out[tid];
    for (int bin = tid; bin < NBINS; bin += BLOCK_THREADS) {
        g_hist_sum[bin] = 0.0;
        g_hist_cnt[bin] = 0u;
    }
    if (tid == 0) {
        g_sum_hard = 0.0; g_cnt_hard = 0ull; g_cnt_valid = 0ull;
        g_pos_loss = 0.0; g_neg_loss = 0.0; g_npos = 0.0; g_reg_sum = 0.0;
        __threadfence();
        g_done = 0u;
    }
}

// ---------------- launch ----------------
extern "C" void kernel_launch(void* const* d_in, const int* in_sizes, int n_in,
                              void* d_out, int out_size)
{
    const float* seg     = (const float*)d_in[0];
    const int*   masks   = (const int*)  d_in[1];
    const float* hm_pred = (const float*)d_in[2];
    const float* hm_tgt  = (const float*)d_in[3];
    const float* wh      = (const float*)d_in[4];
    const float* bboxes  = (const float*)d_in[5];
    // d_in[6] = labels (unused by the reference loss)
    const int*   ct      = (const int*)  d_in[7];
    float* out = (float*)d_out;

    fused_loss_kernel<<<NBLOCKS, BLOCK_THREADS>>>(
        seg, masks, hm_pred, hm_tgt, wh, bboxes, ct, out);
}

// round 12
// speedup vs baseline: 1.0377x; 1.0377x over previous
#include <cuda_runtime.h>
#include <cstdint>

// ---------------- problem shapes (fixed by the dataset) ----------------
constexpr int B    = 8;
constexpr int C    = 19;
constexpr int H    = 512;
constexpr int W    = 1024;
constexpr int HW   = H * W;            // 524288 = 2^19
constexpr int NPIX = B * HW;           // 4194304
constexpr int Hh   = 128;
constexpr int Wh   = 256;
constexpr int HhWh = Hh * Wh;          // 32768
constexpr int NHEAT = B * HhWh;        // 262144
constexpr int NBOX  = 8 * 64;          // 512

constexpr float OHEM_THRESH = 0.22314355513142097f;  // -log(0.8)
constexpr int   NBINS = 4096;
constexpr float BIN_SCALE = (float)NBINS / OHEM_THRESH;
constexpr float F32_TINY = 1.17549435e-38f;
constexpr float L2E  = 1.4426950408889634f;   // log2(e)
constexpr float LN2  = 0.6931471805599453f;   // ln(2)

// ---- hybrid split: consumers LDG channels [0,C_LDG); producer TMAs [C_LDG,19) ----
constexpr int C_LDG = 10;                            // channels via direct LDG
constexpr int C_TMA = C - C_LDG;                     // 9 channels via bulk copy

// ---- pipelined OHEM geometry ----
constexpr int TILE_PIX     = 256;                    // pixels per tile
constexpr int NTILES       = NPIX / TILE_PIX;        // 16384
constexpr int TILES_PER_IMG = HW / TILE_PIX;         // 2048
constexpr int STAGES       = 2;
constexpr int STAGE_BYTES  = C_TMA * TILE_PIX * 4;   // 9216
constexpr int NBLOCKS      = 888;                    // 6 per SM on 148 SMs
constexpr int BLOCK_THREADS = 288;                   // 8 consumer warps + 1 producer
constexpr int FOCAL_BLOCKS = 256;                    // blocks 0..255 pre-do focal

// ---------------- device accumulators (zero at load; final block re-zeros
// them each run so graph replays stay deterministic) ----------------
__device__ double             g_sum_hard;
__device__ unsigned long long g_cnt_hard;
__device__ unsigned long long g_cnt_valid;
__device__ double             g_hist_sum[NBINS];
__device__ unsigned int       g_hist_cnt[NBINS];
__device__ double             g_pos_loss;
__device__ double             g_neg_loss;
__device__ double             g_npos;
__device__ double             g_reg_sum;
__device__ unsigned int       g_done;

__device__ __forceinline__ float ex2f(float x) {
    float r; asm("ex2.approx.ftz.f32 %0, %1;" : "=f"(r) : "f"(x)); return r;
}
__device__ __forceinline__ float lg2f(float x) {
    float r; asm("lg2.approx.ftz.f32 %0, %1;" : "=f"(r) : "f"(x)); return r;
}
__device__ __forceinline__ uint32_t smem_u32(const void* p) {
    uint32_t a;
    asm("{ .reg .u64 t; cvta.to.shared.u64 t, %1; cvt.u32.u64 %0, t; }" : "=r"(a) : "l"(p));
    return a;
}
__device__ __forceinline__ void mbar_init(uint32_t mbar, uint32_t count) {
    asm volatile("mbarrier.init.shared.b64 [%0], %1;" :: "r"(mbar), "r"(count) : "memory");
}
__device__ __forceinline__ void mbar_expect_tx(uint32_t mbar, uint32_t bytes) {
    asm volatile("mbarrier.arrive.expect_tx.shared.b64 _, [%0], %1;"
                 :: "r"(mbar), "r"(bytes) : "memory");
}
__device__ __forceinline__ void mbar_arrive(uint32_t mbar) {
    asm volatile("mbarrier.arrive.shared.b64 _, [%0];" :: "r"(mbar) : "memory");
}
__device__ __forceinline__ void bulk_g2s(uint32_t dst, const void* src,
                                         uint32_t bytes, uint32_t mbar) {
    asm volatile(
        "cp.async.bulk.shared::cluster.global.mbarrier::complete_tx::bytes [%0], [%1], %2, [%3];"
        :: "r"(dst), "l"(src), "r"(bytes), "r"(mbar) : "memory");
}
__device__ __forceinline__ void mbar_wait(uint32_t mbar, uint32_t phase) {
    uint32_t done;
    asm volatile(
        "{\n\t.reg .pred p;\n\t"
        "mbarrier.try_wait.parity.acquire.cta.shared::cta.b64 p, [%1], %2;\n\t"
        "selp.b32 %0, 1, 0, p;\n\t}"
        : "=r"(done) : "r"(mbar), "r"(phase) : "memory");
    while (!done) {
        asm volatile(
            "{\n\t.reg .pred p;\n\t"
            "mbarrier.try_wait.parity.acquire.cta.shared::cta.b64 p, [%1], %2, 0x989680;\n\t"
            "selp.b32 %0, 1, 0, p;\n\t}"
            : "=r"(done) : "r"(mbar), "r"(phase) : "memory");
    }
}

// ---------------- one fused, persistent, hybrid LDG+TMA kernel ----------------
__global__ __launch_bounds__(BLOCK_THREADS, 6) void fused_loss_kernel(
    const float* __restrict__ seg,     const int*   __restrict__ masks,
    const float* __restrict__ hm_pred, const float* __restrict__ hm_tgt,
    const float* __restrict__ wh,      const float* __restrict__ bboxes,
    const int*   __restrict__ ct,      float* __restrict__ out)
{
    const int bid  = blockIdx.x;
    const int tid  = threadIdx.x;
    const int lane = tid & 31, wid = tid >> 5;

    __shared__ alignas(16) float s_stage[STAGES][C_TMA][TILE_PIX];   // 18432 B
    __shared__ alignas(8)  unsigned long long s_full[STAGES], s_empty[STAGES];
    __shared__ float    s_f0[9];
    __shared__ unsigned s_u0[9], s_u1[9];

    if (tid == 0) {
        #pragma unroll
        for (int s = 0; s < STAGES; s++) {
            mbar_init(smem_u32(&s_full[s]), 1);    // expect_tx arrival only
            mbar_init(smem_u32(&s_empty[s]), 8);   // one arrive per consumer warp
        }
    }
    __syncthreads();

    // tiles for this block, grid-strided: T = bid + i*NBLOCKS
    const int nt = (NTILES - bid + NBLOCKS - 1) / NBLOCKS;

    float    fs = 0.0f;
    unsigned hc = 0, vc = 0;

    if (wid == 8) {
        // =================== producer warp: channels [C_LDG, 19) ===================
        for (int i = 0; i < nt; i++) {
            int s = i & 1;
            int k = i >> 1;
            mbar_wait(smem_u32(&s_empty[s]), (k & 1) ^ 1);   // first visit passes
            int T    = bid + i * NBLOCKS;
            int b    = T >> 11;                               // / TILES_PER_IMG
            int pix0 = (T & (TILES_PER_IMG - 1)) * TILE_PIX;
            const float* src = seg + (size_t)b * C * HW + pix0;
            if (lane == 0) mbar_expect_tx(smem_u32(&s_full[s]), STAGE_BYTES);
            __syncwarp();
            if (lane < C_TMA)
                bulk_g2s(smem_u32(&s_stage[s][lane][0]),
                         src + (size_t)(C_LDG + lane) * HW, TILE_PIX * 4,
                         smem_u32(&s_full[s]));
        }
    } else {
        // =================== consumer warps (256 threads) ===================
        // ---- pre-work: focal (bid<256) / regression (bid==256), no block sync ----
        if (bid < FOCAL_BLOCKS) {
            int i4 = bid * 256 + tid;                 // NHEAT/4 = 65536 float4s
            float4 pv  = __ldcs((const float4*)hm_pred + i4);
            float4 tv4 = __ldcs((const float4*)hm_tgt + i4);
            float pl = 0.0f, nl = 0.0f, np = 0.0f;
            const float* pp = &pv.x;
            const float* tp = &tv4.x;
            #pragma unroll
            for (int k = 0; k < 4; k++) {
                float p = fmaxf(pp[k], F32_TINY);
                float t = tp[k];
                if (t == 1.0f) {
                    float om = 1.0f - p;
                    pl += lg2f(p) * LN2 * om * om;
                    np += 1.0f;
                } else {
                    float omt = 1.0f - t;
                    float wgt = omt * omt; wgt *= wgt;
                    nl += lg2f(1.0f - p + F32_TINY) * LN2 * p * p * wgt;
                }
            }
            #pragma unroll
            for (int o = 16; o > 0; o >>= 1) {
                pl += __shfl_xor_sync(0xffffffffu, pl, o);
                nl += __shfl_xor_sync(0xffffffffu, nl, o);
                np += __shfl_xor_sync(0xffffffffu, np, o);
            }
            if (lane == 0) {
                atomicAdd(&g_pos_loss, (double)pl);
                atomicAdd(&g_neg_loss, (double)nl);
                atomicAdd(&g_npos,     (double)np);
            }
        } else if (bid == FOCAL_BLOCKS) {
            float l1 = 0.0f;
            #pragma unroll
            for (int r = 0; r < 2; r++) {
                int i = tid + r * 256;
                int b = i >> 6;
                int x = ct[i * 2 + 0];
                int y = ct[i * 2 + 1];
                const float* whb = wh + (size_t)b * 2 * HhWh;
                float v0 = whb[y * Wh + x];
                float v1 = whb[HhWh + y * Wh + x];
                const float* bb = bboxes + (size_t)i * 4;
                float w = bb[2] - bb[0];
                float h = bb[3] - bb[1];
                l1 += fabsf(v0 - w) + fabsf(v1 - h);
            }
            #pragma unroll
            for (int o = 16; o > 0; o >>= 1) l1 += __shfl_xor_sync(0xffffffffu, l1, o);
            if (lane == 0) atomicAdd(&g_reg_sum, (double)l1);
        }

        // ---- OHEM tile loop: LDG channels 0..9 + SMEM channels 10..18 ----
        for (int i = 0; i < nt; i++) {
            int s = i & 1;
            int k = i >> 1;
            int T    = bid + i * NBLOCKS;
            int b    = T >> 11;
            int pix0 = (T & (TILES_PER_IMG - 1)) * TILE_PIX;
            const float* src = seg + (size_t)b * C * HW + pix0 + tid;

            int t = __ldcs(masks + (size_t)b * HW + pix0 + tid);

            // LDG half (independent of pipeline — overlaps the bulk copies)
            float sum = 0.0f, xtL = 0.0f;
            #pragma unroll
            for (int c = 0; c < C_LDG; c++) {
                float v = __ldcs(src + (size_t)c * HW);
                sum += ex2f(v * L2E);
                xtL = (c == t) ? v : xtL;
            }

            // SMEM half
            mbar_wait(smem_u32(&s_full[s]), k & 1);
            const float* st = &s_stage[s][0][0];
            #pragma unroll
            for (int c = 0; c < C_TMA; c++)
                sum += ex2f(st[c * TILE_PIX + tid] * L2E);

            bool valid = (t != 255);
            float xt = (t >= C_LDG && valid) ? st[(t - C_LDG) * TILE_PIX + tid] : xtL;
            float ce = valid ? __fmaf_rn(lg2f(sum), LN2, -xt) : 0.0f;
            bool hd = ce > OHEM_THRESH;

            fs += hd ? ce : 0.0f;
            hc += (unsigned)hd;
            vc += (unsigned)valid;
            if (!hd) {   // rare: ce <= THRESH -> global histogram
                int bin = min(max((int)(ce * BIN_SCALE), 0), NBINS - 1);
                atomicAdd(&g_hist_cnt[bin], 1u);
                atomicAdd(&g_hist_sum[bin], (double)ce);
            }

            __syncwarp();                      // all lanes done reading stage
            if (lane == 0) mbar_arrive(smem_u32(&s_empty[s]));
        }
    }

    // =================== block reduction (producer contributes zeros) ===========
    #pragma unroll
    for (int o = 16; o > 0; o >>= 1) {
        fs += __shfl_xor_sync(0xffffffffu, fs, o);
        hc += __shfl_xor_sync(0xffffffffu, hc, o);
        vc += __shfl_xor_sync(0xffffffffu, vc, o);
    }
    if (lane == 0) { s_f0[wid] = fs; s_u0[wid] = hc; s_u1[wid] = vc; }
    __syncthreads();
    if (tid == 0) {
        double ts = 0.0; unsigned th = 0, tv = 0;
        #pragma unroll
        for (int i = 0; i < 9; i++) { ts += (double)s_f0[i]; th += s_u0[i]; tv += s_u1[i]; }
        if (th | tv) {
            atomicAdd(&g_sum_hard, ts);
            atomicAdd(&g_cnt_hard, (unsigned long long)th);
            atomicAdd(&g_cnt_valid, (unsigned long long)tv);
        }
    }

    // ===================== last-block election =====================
    __shared__ bool s_last;
    __syncthreads();
    if (tid == 0) {
        __threadfence();
        unsigned prev = atomicAdd(&g_done, 1u);
        s_last = (prev == (unsigned)(NBLOCKS - 1));
    }
    __syncthreads();
    if (!s_last) return;
    __threadfence();

    __shared__ float s_out[4];
    if (tid == 0) {
        // classification (OHEM)
        unsigned long long nmin = g_cnt_valid / 16ull;
        double k, top;
        if (g_cnt_hard >= nmin) {
            k = (double)g_cnt_hard;
            top = g_sum_hard;
        } else {
            k = (double)nmin;
            top = g_sum_hard;
            double need = (double)(nmin - g_cnt_hard);
            for (int bin = NBINS - 1; bin >= 0 && need > 0.0; --bin) {
                unsigned c = g_hist_cnt[bin];
                if (!c) continue;
                if ((double)c <= need) { top += g_hist_sum[bin]; need -= (double)c; }
                else                   { top += g_hist_sum[bin] * (need / (double)c); need = 0.0; }
            }
        }
        float cls = (k > 0.0) ? (float)(top / k) : 0.0f;

        // centerness (focal)
        double npos = g_npos;
        double fl = (npos == 0.0) ? -g_neg_loss
                                  : -(g_pos_loss + g_neg_loss) / fmax(npos, 1.0);
        float centerness = (float)fl;

        // bbox
        float regression = (float)g_reg_sum * 0.7f;
        float bbox = regression / ((float)NBOX + 1e-7f) * 0.1f;
        float localization = (centerness + bbox) * 1.0f;

        s_out[0] = cls;
        s_out[1] = localization;
        s_out[2] = centerness;
        s_out[3] = bbox;
    }
    __syncthreads();

    if (tid < 4) out[tid] = s_out[tid];
    for (int bin = tid; bin < NBINS; bin += BLOCK_THREADS) {
        g_hist_sum[bin] = 0.0;
        g_hist_cnt[bin] = 0u;
    }
    if (tid == 0) {
        g_sum_hard = 0.0; g_cnt_hard = 0ull; g_cnt_valid = 0ull;
        g_pos_loss = 0.0; g_neg_loss = 0.0; g_npos = 0.0; g_reg_sum = 0.0;
        __threadfence();
        g_done = 0u;
    }
}

// ---------------- launch ----------------
extern "C" void kernel_launch(void* const* d_in, const int* in_sizes, int n_in,
                              void* d_out, int out_size)
{
    const float* seg     = (const float*)d_in[0];
    const int*   masks   = (const int*)  d_in[1];
    const float* hm_pred = (const float*)d_in[2];
    const float* hm_tgt  = (const float*)d_in[3];
    const float* wh      = (const float*)d_in[4];
    const float* bboxes  = (const float*)d_in[5];
    // d_in[6] = labels (unused by the reference loss)
    const int*   ct      = (const int*)  d_in[7];
    float* out = (float*)d_out;

    fused_loss_kernel<<<NBLOCKS, BLOCK_THREADS>>>(
        seg, masks, hm_pred, hm_tgt, wh, bboxes, ct, out);
}